// round 3
// baseline (speedup 1.0000x reference)
#include <cuda_runtime.h>
#include <cstdint>

#define NN 50000
#define NE 1600000
#define IND 128
#define HD 64
#define NR 5
#define SA_STRIDE 68
#define TPAD 72
#define NEG_SLOPE 0.01f

// ---- scratch (device globals; no allocation allowed) ----
__device__ float g_w[NE];
__device__ float g_S[NN * NR];
__device__ float g_emb0[NN * HD];
__device__ float g_emb1[NN * HD];
__device__ float g_emb2[NN * HD];
__device__ float g_T[(size_t)10 * NN * HD];     // TA_r at idx r (0..4), TB_r at idx 5+r
__device__ float g_acc[NN * HD];

// ---------------------------------------------------------------------------
__global__ void k_init() {
  int stride = gridDim.x * blockDim.x;
  int t = blockIdx.x * blockDim.x + threadIdx.x;
  for (int i = t; i < NN * NR; i += stride) g_S[i] = 0.f;
  for (int i = t; i < NN * HD; i += stride) g_acc[i] = 0.f;
}

__global__ void k_wS(const float* __restrict__ etime, const int* __restrict__ eidx,
                     const int* __restrict__ etype, const float* __restrict__ plam,
                     const float* __restrict__ pbeta) {
  int e = blockIdx.x * blockDim.x + threadIdx.x;
  if (e >= NE) return;
  float w = plam[0] * expf(-pbeta[0] * fabsf(etime[e]));
  g_w[e] = w;
  int d = eidx[NE + e];
  int r = etype[e];
  atomicAdd(&g_S[d * NR + r], w);
}

// ---------------------------------------------------------------------------
// tf32 helpers
__device__ __forceinline__ uint32_t f2tf(float f) {
  uint32_t r;
  asm("cvt.rna.tf32.f32 %0, %1;" : "=r"(r) : "f"(f));
  return r;
}
__device__ __forceinline__ void split_tf(float f, uint32_t& hi, uint32_t& lo) {
  hi = f2tf(f);
  lo = f2tf(f - __uint_as_float(hi));
}
__device__ __forceinline__ void mma_tf32(float c[4], uint32_t a0, uint32_t a1,
                                         uint32_t a2, uint32_t a3,
                                         uint32_t b0, uint32_t b1) {
  asm volatile(
      "mma.sync.aligned.m16n8k8.row.col.f32.tf32.tf32.f32 "
      "{%0,%1,%2,%3}, {%4,%5,%6,%7}, {%8,%9}, {%0,%1,%2,%3};"
      : "+f"(c[0]), "+f"(c[1]), "+f"(c[2]), "+f"(c[3])
      : "r"(a0), "r"(a1), "r"(a2), "r"(a3), "r"(b0), "r"(b1));
}

// k_trans: T[idx] = emb @ W_slice for idx 0..9, 3xTF32 tensor-core GEMM.
// Block: 128 threads (4 warps), 64-row tile; A transposed in smem (reused 10x).
__global__ void __launch_bounds__(128) k_trans(const float* __restrict__ relW, int layer) {
  extern __shared__ __align__(16) float smem[];
  float* sAt = smem;                                   // [64 k][TPAD] transposed A
  uint32_t* sWhi = (uint32_t*)(smem + 64 * TPAD);      // [64 k][TPAD]
  uint32_t* sWlo = (uint32_t*)(smem + 2 * 64 * TPAD);  // [64 k][TPAD]

  const float* emb = (layer == 0) ? g_emb0 : g_emb1;
  int tid = threadIdx.x;
  int lane = tid & 31, warp = tid >> 5;
  int g = lane >> 2, tg = lane & 3;
  int wrow = warp * 16;
  int row0 = blockIdx.x * 64;

  // Load A tile [64 rows x 64 k] transposed -> sAt[k][row], zero-pad OOB rows.
  #pragma unroll 1
  for (int i = tid; i < 64 * 16; i += 128) {
    int r = i >> 4, c4 = i & 15;
    float4 v = make_float4(0.f, 0.f, 0.f, 0.f);
    if (row0 + r < NN) v = *(const float4*)(emb + (size_t)(row0 + r) * HD + c4 * 4);
    sAt[(c4 * 4 + 0) * TPAD + r] = v.x;
    sAt[(c4 * 4 + 1) * TPAD + r] = v.y;
    sAt[(c4 * 4 + 2) * TPAD + r] = v.z;
    sAt[(c4 * 4 + 3) * TPAD + r] = v.w;
  }

  #pragma unroll 1
  for (int idx = 0; idx < 10; idx++) {
    int r = (idx < 5) ? idx : idx - 5;
    int half = (idx < 5) ? 0 : 1;
    const float* W = relW + (size_t)r * (2 * HD) * HD + (size_t)half * HD * HD;

    __syncthreads();  // A ready (first iter) / previous mma reads done
    // Split W into tf32 hi/lo in smem.
    #pragma unroll 1
    for (int i = tid; i < HD * HD; i += 128) {
      int k = i >> 6, n = i & 63;
      uint32_t hi, lo;
      split_tf(__ldg(&W[i]), hi, lo);
      sWhi[k * TPAD + n] = hi;
      sWlo[k * TPAD + n] = lo;
    }
    __syncthreads();

    float acc[8][4] = {};
    #pragma unroll 1
    for (int k0 = 0; k0 < 64; k0 += 8) {
      float af0 = sAt[(k0 + tg) * TPAD + wrow + g];
      float af1 = sAt[(k0 + tg) * TPAD + wrow + g + 8];
      float af2 = sAt[(k0 + tg + 4) * TPAD + wrow + g];
      float af3 = sAt[(k0 + tg + 4) * TPAD + wrow + g + 8];
      uint32_t ah0, al0, ah1, al1, ah2, al2, ah3, al3;
      split_tf(af0, ah0, al0);
      split_tf(af1, ah1, al1);
      split_tf(af2, ah2, al2);
      split_tf(af3, ah3, al3);
      #pragma unroll
      for (int nc = 0; nc < 8; nc++) {
        uint32_t b0h = sWhi[(k0 + tg) * TPAD + nc * 8 + g];
        uint32_t b1h = sWhi[(k0 + tg + 4) * TPAD + nc * 8 + g];
        uint32_t b0l = sWlo[(k0 + tg) * TPAD + nc * 8 + g];
        uint32_t b1l = sWlo[(k0 + tg + 4) * TPAD + nc * 8 + g];
        mma_tf32(acc[nc], ah0, ah1, ah2, ah3, b0h, b1h);  // hi*hi
        mma_tf32(acc[nc], ah0, ah1, ah2, ah3, b0l, b1l);  // hi*lo
        mma_tf32(acc[nc], al0, al1, al2, al3, b0h, b1h);  // lo*hi
      }
    }

    // Writeback: c0,c1 -> (g, nc*8+2tg), c2,c3 -> (g+8, same cols)
    float* out = g_T + (size_t)idx * NN * HD;
    int ra = row0 + wrow + g;
    int rb = ra + 8;
    #pragma unroll
    for (int nc = 0; nc < 8; nc++) {
      int col = nc * 8 + 2 * tg;
      if (ra < NN)
        *(float2*)(out + (size_t)ra * HD + col) = make_float2(acc[nc][0], acc[nc][1]);
      if (rb < NN)
        *(float2*)(out + (size_t)rb * HD + col) = make_float2(acc[nc][2], acc[nc][3]);
    }
  }
}

// ---------------------------------------------------------------------------
// FFMA helpers for the small GEMMs (emb0, out)
__device__ __forceinline__ void fillA(const float* __restrict__ A, int Kstride, int kofs,
                                      int row0, float* sA) {
  #pragma unroll 1
  for (int i = threadIdx.x; i < 1024; i += 256) {
    int r = i >> 4, c = i & 15;
    int row = row0 + r;
    float4 v = make_float4(0.f, 0.f, 0.f, 0.f);
    if (row < NN) v = *(const float4*)(A + (size_t)row * Kstride + kofs + c * 4);
    *(float4*)(sA + r * SA_STRIDE + c * 4) = v;
  }
}
__device__ __forceinline__ void fillW(const float* __restrict__ W, float* sW) {
  #pragma unroll 1
  for (int i = threadIdx.x; i < 1024; i += 256)
    ((float4*)sW)[i] = ((const float4*)W)[i];
}
__device__ __forceinline__ void mma64(const float* sA, const float* sW,
                                      float acc[4][4], int tx, int ty) {
  #pragma unroll 4
  for (int k = 0; k < 64; k += 4) {
    float4 a[4], w[4];
    #pragma unroll
    for (int i = 0; i < 4; i++)
      a[i] = *(const float4*)(sA + (ty * 4 + i) * SA_STRIDE + k);
    #pragma unroll
    for (int j = 0; j < 4; j++)
      w[j] = *(const float4*)(sW + (k + j) * 64 + tx * 4);
    #pragma unroll
    for (int i = 0; i < 4; i++) {
      acc[i][0] += a[i].x * w[0].x + a[i].y * w[1].x + a[i].z * w[2].x + a[i].w * w[3].x;
      acc[i][1] += a[i].x * w[0].y + a[i].y * w[1].y + a[i].z * w[2].y + a[i].w * w[3].y;
      acc[i][2] += a[i].x * w[0].z + a[i].y * w[1].z + a[i].z * w[2].z + a[i].w * w[3].z;
      acc[i][3] += a[i].x * w[0].w + a[i].y * w[1].w + a[i].z * w[2].w + a[i].w * w[3].w;
    }
  }
}

// emb0 = x @ field_W + field_b
__global__ void k_emb0(const float* __restrict__ x, const float* __restrict__ fW,
                       const float* __restrict__ fb) {
  __shared__ __align__(16) float sA[64 * SA_STRIDE];
  __shared__ __align__(16) float sW[64 * 64];
  __shared__ float sb[64];
  if (threadIdx.x < 64) sb[threadIdx.x] = fb[threadIdx.x];
  int tx = threadIdx.x & 15, ty = threadIdx.x >> 4;
  int row0 = blockIdx.x * 64;
  float acc[4][4] = {};
  #pragma unroll 1
  for (int k0 = 0; k0 < IND; k0 += 64) {
    __syncthreads();
    fillA(x, IND, k0, row0, sA);
    fillW(fW + (size_t)k0 * HD, sW);
    __syncthreads();
    mma64(sA, sW, acc, tx, ty);
  }
  #pragma unroll
  for (int i = 0; i < 4; i++) {
    int row = row0 + ty * 4 + i;
    if (row < NN) {
      float4 o = make_float4(acc[i][0] + sb[tx * 4 + 0], acc[i][1] + sb[tx * 4 + 1],
                             acc[i][2] + sb[tx * 4 + 2], acc[i][3] + sb[tx * 4 + 3]);
      *(float4*)(g_emb0 + (size_t)row * HD + tx * 4) = o;
    }
  }
}

// Per-edge scatter: acc[dst] += w_e * TA[r][src]. 16 lanes/edge, red.v4 atomics.
__global__ void k_edge(const int* __restrict__ eidx, const int* __restrict__ etype) {
  int gid = blockIdx.x * 256 + threadIdx.x;
  int e = gid >> 4;
  int lane = gid & 15;
  int s = __ldg(&eidx[e]);
  int d = __ldg(&eidx[NE + e]);
  int r = __ldg(&etype[e]);
  float w = __ldg(&g_w[e]);
  const float4* rowp = (const float4*)(g_T + ((size_t)r * NN + s) * HD);
  float4 v = __ldg(rowp + lane);
  float* dp = g_acc + (size_t)d * HD + lane * 4;
  asm volatile("red.global.add.v4.f32 [%0], {%1,%2,%3,%4};"
               :: "l"(dp), "f"(v.x * w), "f"(v.y * w), "f"(v.z * w), "f"(v.w * w)
               : "memory");
}

// emb_out[n] = acc[n] + sum_r S[n][r]*(TB_r[n] + b_r); re-zeros acc.
__global__ void k_dst(const float* __restrict__ relb, int layer) {
  __shared__ float sb[NR * HD];
  for (int i = threadIdx.x; i < NR * HD; i += blockDim.x) sb[i] = relb[i];
  __syncthreads();
  float* emb = (layer == 0) ? g_emb1 : g_emb2;
  int t = blockIdx.x * 256 + threadIdx.x;
  int node = t >> 4, lane = t & 15;
  if (node >= NN) return;
  float4 a = *(float4*)(g_acc + (size_t)node * HD + lane * 4);
  #pragma unroll
  for (int r = 0; r < NR; r++) {
    float s = g_S[node * NR + r];
    float4 t4 = __ldg((const float4*)(g_T + (size_t)(5 + r) * NN * HD + (size_t)node * HD) + lane);
    float4 b4 = *(float4*)(sb + r * HD + lane * 4);
    a.x += s * (t4.x + b4.x);
    a.y += s * (t4.y + b4.y);
    a.z += s * (t4.z + b4.z);
    a.w += s * (t4.w + b4.w);
  }
  *(float4*)(emb + (size_t)node * HD + lane * 4) = a;
  *(float4*)(g_acc + (size_t)node * HD + lane * 4) = make_float4(0.f, 0.f, 0.f, 0.f);
}

// out = sum_j leaky_relu(emb_j @ outW_j + outb_j), fused over j=0..2.
__global__ void k_out(const float* __restrict__ W0, const float* __restrict__ b0,
                      const float* __restrict__ W1, const float* __restrict__ b1,
                      const float* __restrict__ W2, const float* __restrict__ b2,
                      float* __restrict__ out) {
  __shared__ __align__(16) float sA[64 * SA_STRIDE];
  __shared__ __align__(16) float sW[64 * 64];
  __shared__ float sb[64];
  int tx = threadIdx.x & 15, ty = threadIdx.x >> 4;
  int row0 = blockIdx.x * 64;
  float o[4][4] = {};
  #pragma unroll 1
  for (int j = 0; j < 3; j++) {
    const float* emb = (j == 0) ? g_emb0 : (j == 1) ? g_emb1 : g_emb2;
    const float* W = (j == 0) ? W0 : (j == 1) ? W1 : W2;
    const float* b = (j == 0) ? b0 : (j == 1) ? b1 : b2;
    __syncthreads();
    if (threadIdx.x < 64) sb[threadIdx.x] = b[threadIdx.x];
    fillA(emb, HD, 0, row0, sA);
    fillW(W, sW);
    __syncthreads();
    float acc[4][4] = {};
    mma64(sA, sW, acc, tx, ty);
    #pragma unroll
    for (int i = 0; i < 4; i++)
      #pragma unroll
      for (int m = 0; m < 4; m++) {
        float z = acc[i][m] + sb[tx * 4 + m];
        o[i][m] += (z >= 0.f) ? z : NEG_SLOPE * z;
      }
  }
  #pragma unroll
  for (int i = 0; i < 4; i++) {
    int row = row0 + ty * 4 + i;
    if (row < NN)
      *(float4*)(out + (size_t)row * HD + tx * 4) =
          make_float4(o[i][0], o[i][1], o[i][2], o[i][3]);
  }
}

// ---------------------------------------------------------------------------
extern "C" void kernel_launch(void* const* d_in, const int* in_sizes, int n_in,
                              void* d_out, int out_size) {
  const float* x     = (const float*)d_in[0];
  const int*   eidx  = (const int*)d_in[1];
  const int*   etype = (const int*)d_in[2];
  const float* etime = (const float*)d_in[3];
  const float* fW    = (const float*)d_in[4];
  const float* fb    = (const float*)d_in[5];
  const float* rW1   = (const float*)d_in[6];
  const float* rb1   = (const float*)d_in[7];
  const float* rW2   = (const float*)d_in[8];
  const float* rb2   = (const float*)d_in[9];
  const float* oW0   = (const float*)d_in[10];
  const float* ob0   = (const float*)d_in[11];
  const float* oW1   = (const float*)d_in[12];
  const float* ob1   = (const float*)d_in[13];
  const float* oW2   = (const float*)d_in[14];
  const float* ob2   = (const float*)d_in[15];
  const float* lam   = (const float*)d_in[16];
  const float* beta  = (const float*)d_in[17];
  float* out = (float*)d_out;

  const int GB = (NN + 63) / 64;  // 782 row tiles
  const int TRANS_SMEM = 3 * 64 * TPAD * 4;  // 55296 B
  cudaFuncSetAttribute(k_trans, cudaFuncAttributeMaxDynamicSharedMemorySize, TRANS_SMEM);

  k_init<<<1024, 256>>>();
  k_wS<<<(NE + 255) / 256, 256>>>(etime, eidx, etype, lam, beta);
  k_emb0<<<GB, 256>>>(x, fW, fb);

  // layer 1
  k_trans<<<GB, 128, TRANS_SMEM>>>(rW1, 0);
  k_edge<<<NE * 16 / 256, 256>>>(eidx, etype);
  k_dst<<<(NN * 16 + 255) / 256, 256>>>(rb1, 0);

  // layer 2
  k_trans<<<GB, 128, TRANS_SMEM>>>(rW2, 1);
  k_edge<<<NE * 16 / 256, 256>>>(eidx, etype);
  k_dst<<<(NN * 16 + 255) / 256, 256>>>(rb2, 1);

  k_out<<<GB, 256>>>(oW0, ob0, oW1, ob1, oW2, ob2, out);
}

// round 4
// speedup vs baseline: 1.5169x; 1.5169x over previous
#include <cuda_runtime.h>

#define NN 50000
#define NE 1600000
#define IND 128
#define HD 64
#define NR 5
#define SA_STRIDE 68
#define NEG_SLOPE 0.01f

// ---- scratch (device globals; no allocation allowed) ----
__device__ float g_w[NE];
__device__ float g_S[NN * NR];
__device__ float g_emb0[NN * HD];
__device__ float g_emb1[NN * HD];
__device__ float g_emb2[NN * HD];
__device__ float g_T[(size_t)10 * NN * HD];     // TA_r at idx r (0..4), TB_r at idx 5+r
__device__ float g_acc[NN * HD];

// ---------------------------------------------------------------------------
__global__ void k_init() {
  int stride = gridDim.x * blockDim.x;
  int t = blockIdx.x * blockDim.x + threadIdx.x;
  for (int i = t; i < NN * NR; i += stride) g_S[i] = 0.f;
  for (int i = t; i < NN * HD; i += stride) g_acc[i] = 0.f;
}

__global__ void k_wS(const float* __restrict__ etime, const int* __restrict__ eidx,
                     const int* __restrict__ etype, const float* __restrict__ plam,
                     const float* __restrict__ pbeta) {
  int e = blockIdx.x * blockDim.x + threadIdx.x;
  if (e >= NE) return;
  float w = plam[0] * expf(-pbeta[0] * fabsf(etime[e]));
  g_w[e] = w;
  int d = eidx[NE + e];
  int r = etype[e];
  atomicAdd(&g_S[d * NR + r], w);
}

// ---------------------------------------------------------------------------
// Fill 64-row x 64-col A tile into smem (row-major, stride SA_STRIDE).
__device__ __forceinline__ void fillA(const float* __restrict__ A, int Kstride, int kofs,
                                      int row0, float* sA) {
  #pragma unroll 1
  for (int i = threadIdx.x; i < 1024; i += 256) {
    int r = i >> 4, c = i & 15;
    int row = row0 + r;
    float4 v = make_float4(0.f, 0.f, 0.f, 0.f);
    if (row < NN) v = *(const float4*)(A + (size_t)row * Kstride + kofs + c * 4);
    *(float4*)(sA + r * SA_STRIDE + c * 4) = v;
  }
}
__device__ __forceinline__ void fillW(const float* __restrict__ W, float* sW) {
  #pragma unroll 1
  for (int i = threadIdx.x; i < 1024; i += 256)
    ((float4*)sW)[i] = ((const float4*)W)[i];
}

// 64x64 @ 64x64 inner product, k unrolled by 4, all-float4 LDS.
// Each thread: 4 rows (ty*4..+3) x 4 cols (tx*4..+3).
__device__ __forceinline__ void mma64(const float* sA, const float* sW,
                                      float acc[4][4], int tx, int ty) {
  #pragma unroll 4
  for (int k = 0; k < 64; k += 4) {
    float4 a[4], w[4];
    #pragma unroll
    for (int i = 0; i < 4; i++)
      a[i] = *(const float4*)(sA + (ty * 4 + i) * SA_STRIDE + k);
    #pragma unroll
    for (int j = 0; j < 4; j++)
      w[j] = *(const float4*)(sW + (k + j) * 64 + tx * 4);
    #pragma unroll
    for (int i = 0; i < 4; i++) {
      acc[i][0] += a[i].x * w[0].x + a[i].y * w[1].x + a[i].z * w[2].x + a[i].w * w[3].x;
      acc[i][1] += a[i].x * w[0].y + a[i].y * w[1].y + a[i].z * w[2].y + a[i].w * w[3].y;
      acc[i][2] += a[i].x * w[0].z + a[i].y * w[1].z + a[i].z * w[2].z + a[i].w * w[3].z;
      acc[i][3] += a[i].x * w[0].w + a[i].y * w[1].w + a[i].z * w[2].w + a[i].w * w[3].w;
    }
  }
}

// emb0 = x @ field_W + field_b   (K = 128, two k-tiles)
__global__ void k_emb0(const float* __restrict__ x, const float* __restrict__ fW,
                       const float* __restrict__ fb) {
  __shared__ __align__(16) float sA[64 * SA_STRIDE];
  __shared__ __align__(16) float sW[64 * 64];
  __shared__ float sb[64];
  if (threadIdx.x < 64) sb[threadIdx.x] = fb[threadIdx.x];
  int tx = threadIdx.x & 15, ty = threadIdx.x >> 4;
  int row0 = blockIdx.x * 64;
  float acc[4][4] = {};
  #pragma unroll 1
  for (int k0 = 0; k0 < IND; k0 += 64) {
    __syncthreads();
    fillA(x, IND, k0, row0, sA);
    fillW(fW + (size_t)k0 * HD, sW);
    __syncthreads();
    mma64(sA, sW, acc, tx, ty);
  }
  #pragma unroll
  for (int i = 0; i < 4; i++) {
    int row = row0 + ty * 4 + i;
    if (row < NN) {
      float4 o = make_float4(acc[i][0] + sb[tx * 4 + 0], acc[i][1] + sb[tx * 4 + 1],
                             acc[i][2] + sb[tx * 4 + 2], acc[i][3] + sb[tx * 4 + 3]);
      *(float4*)(g_emb0 + (size_t)row * HD + tx * 4) = o;
    }
  }
}

// T[idx] = emb @ W_slice, one (row-tile, idx) GEMM per block. idx = blockIdx.y.
__global__ void k_trans(const float* __restrict__ relW, int layer) {
  __shared__ __align__(16) float sA[64 * SA_STRIDE];
  __shared__ __align__(16) float sW[64 * 64];
  const float* emb = (layer == 0) ? g_emb0 : g_emb1;
  int idx = blockIdx.y;
  int r = idx % 5, half = idx / 5;
  const float* W = relW + ((size_t)r * (2 * HD) + half * HD) * HD;
  int tx = threadIdx.x & 15, ty = threadIdx.x >> 4;
  int row0 = blockIdx.x * 64;
  fillA(emb, HD, 0, row0, sA);
  fillW(W, sW);
  __syncthreads();
  float acc[4][4] = {};
  mma64(sA, sW, acc, tx, ty);
  float* out = g_T + (size_t)idx * NN * HD;
  #pragma unroll
  for (int i = 0; i < 4; i++) {
    int row = row0 + ty * 4 + i;
    if (row < NN)
      *(float4*)(out + (size_t)row * HD + tx * 4) =
          make_float4(acc[i][0], acc[i][1], acc[i][2], acc[i][3]);
  }
}

// Per-edge scatter: acc[dst] += w_e * TA[r][src]. 16 lanes/edge, red.v4 atomics.
__global__ void k_edge(const int* __restrict__ eidx, const int* __restrict__ etype) {
  int gid = blockIdx.x * 256 + threadIdx.x;
  int e = gid >> 4;
  int lane = gid & 15;
  int s = __ldg(&eidx[e]);
  int d = __ldg(&eidx[NE + e]);
  int r = __ldg(&etype[e]);
  float w = __ldg(&g_w[e]);
  const float4* rowp = (const float4*)(g_T + ((size_t)r * NN + s) * HD);
  float4 v = __ldg(rowp + lane);
  float* dp = g_acc + (size_t)d * HD + lane * 4;
  asm volatile("red.global.add.v4.f32 [%0], {%1,%2,%3,%4};"
               :: "l"(dp), "f"(v.x * w), "f"(v.y * w), "f"(v.z * w), "f"(v.w * w)
               : "memory");
}

// emb_out[n] = acc[n] + sum_r S[n][r]*(TB_r[n] + b_r); re-zeros acc.
__global__ void k_dst(const float* __restrict__ relb, int layer) {
  __shared__ float sb[NR * HD];
  for (int i = threadIdx.x; i < NR * HD; i += blockDim.x) sb[i] = relb[i];
  __syncthreads();
  float* emb = (layer == 0) ? g_emb1 : g_emb2;
  int t = blockIdx.x * 256 + threadIdx.x;
  int node = t >> 4, lane = t & 15;
  if (node >= NN) return;
  float4 a = *(float4*)(g_acc + (size_t)node * HD + lane * 4);
  #pragma unroll
  for (int r = 0; r < NR; r++) {
    float s = g_S[node * NR + r];
    float4 t4 = __ldg((const float4*)(g_T + (size_t)(5 + r) * NN * HD + (size_t)node * HD) + lane);
    float4 b4 = *(float4*)(sb + r * HD + lane * 4);
    a.x += s * (t4.x + b4.x);
    a.y += s * (t4.y + b4.y);
    a.z += s * (t4.z + b4.z);
    a.w += s * (t4.w + b4.w);
  }
  *(float4*)(emb + (size_t)node * HD + lane * 4) = a;
  *(float4*)(g_acc + (size_t)node * HD + lane * 4) = make_float4(0.f, 0.f, 0.f, 0.f);
}

// out = sum_j leaky_relu(emb_j @ outW_j + outb_j), fused over j=0..2.
__global__ void k_out(const float* __restrict__ W0, const float* __restrict__ b0,
                      const float* __restrict__ W1, const float* __restrict__ b1,
                      const float* __restrict__ W2, const float* __restrict__ b2,
                      float* __restrict__ out) {
  __shared__ __align__(16) float sA[64 * SA_STRIDE];
  __shared__ __align__(16) float sW[64 * 64];
  __shared__ float sb[64];
  int tx = threadIdx.x & 15, ty = threadIdx.x >> 4;
  int row0 = blockIdx.x * 64;
  float o[4][4] = {};
  #pragma unroll 1
  for (int j = 0; j < 3; j++) {
    const float* emb = (j == 0) ? g_emb0 : (j == 1) ? g_emb1 : g_emb2;
    const float* W = (j == 0) ? W0 : (j == 1) ? W1 : W2;
    const float* b = (j == 0) ? b0 : (j == 1) ? b1 : b2;
    __syncthreads();
    if (threadIdx.x < 64) sb[threadIdx.x] = b[threadIdx.x];
    fillA(emb, HD, 0, row0, sA);
    fillW(W, sW);
    __syncthreads();
    float acc[4][4] = {};
    mma64(sA, sW, acc, tx, ty);
    #pragma unroll
    for (int i = 0; i < 4; i++)
      #pragma unroll
      for (int m = 0; m < 4; m++) {
        float z = acc[i][m] + sb[tx * 4 + m];
        o[i][m] += (z >= 0.f) ? z : NEG_SLOPE * z;
      }
  }
  #pragma unroll
  for (int i = 0; i < 4; i++) {
    int row = row0 + ty * 4 + i;
    if (row < NN)
      *(float4*)(out + (size_t)row * HD + tx * 4) =
          make_float4(o[i][0], o[i][1], o[i][2], o[i][3]);
  }
}

// ---------------------------------------------------------------------------
extern "C" void kernel_launch(void* const* d_in, const int* in_sizes, int n_in,
                              void* d_out, int out_size) {
  const float* x     = (const float*)d_in[0];
  const int*   eidx  = (const int*)d_in[1];
  const int*   etype = (const int*)d_in[2];
  const float* etime = (const float*)d_in[3];
  const float* fW    = (const float*)d_in[4];
  const float* fb    = (const float*)d_in[5];
  const float* rW1   = (const float*)d_in[6];
  const float* rb1   = (const float*)d_in[7];
  const float* rW2   = (const float*)d_in[8];
  const float* rb2   = (const float*)d_in[9];
  const float* oW0   = (const float*)d_in[10];
  const float* ob0   = (const float*)d_in[11];
  const float* oW1   = (const float*)d_in[12];
  const float* ob1   = (const float*)d_in[13];
  const float* oW2   = (const float*)d_in[14];
  const float* ob2   = (const float*)d_in[15];
  const float* lam   = (const float*)d_in[16];
  const float* beta  = (const float*)d_in[17];
  float* out = (float*)d_out;

  const int GB = (NN + 63) / 64;  // 782 row tiles
  dim3 gt(GB, 10);                // one GEMM per block (R1 shape, improved inner loop)

  k_init<<<1024, 256>>>();
  k_wS<<<(NE + 255) / 256, 256>>>(etime, eidx, etype, lam, beta);
  k_emb0<<<GB, 256>>>(x, fW, fb);

  // layer 1
  k_trans<<<gt, 256>>>(rW1, 0);
  k_edge<<<NE * 16 / 256, 256>>>(eidx, etype);
  k_dst<<<(NN * 16 + 255) / 256, 256>>>(rb1, 0);

  // layer 2
  k_trans<<<gt, 256>>>(rW2, 1);
  k_edge<<<NE * 16 / 256, 256>>>(eidx, etype);
  k_dst<<<(NN * 16 + 255) / 256, 256>>>(rb2, 1);

  k_out<<<GB, 256>>>(oW0, ob0, oW1, ob1, oW2, ob2, out);
}

// round 5
// speedup vs baseline: 1.7742x; 1.1696x over previous
#include <cuda_runtime.h>

#define NN 50000
#define NE 1600000
#define IND 128
#define HD 64
#define NR 5
#define SA_STRIDE 68
#define NEG_SLOPE 0.01f
#define NCHUNK 196   // ceil(50000/256)

// ---- scratch (device globals; no allocation allowed) ----
__device__ float g_w[NE];
__device__ float g_S[NN * NR];
__device__ int   g_deg[NN];
__device__ int   g_off[NN + 1];
__device__ int   g_part[256];
__device__ int   g_cur[NN];
__device__ int   g_cmeta[NE];     // src | (r<<16)
__device__ float g_cw[NE];
__device__ float g_emb0[NN * HD];
__device__ float g_emb1[NN * HD];
__device__ float g_emb2[NN * HD];
__device__ float g_T[(size_t)10 * NN * HD];  // TA_r at idx r (0..4), TB_r at idx 5+r

// ---------------------------------------------------------------------------
__global__ void k_zero() {
  int stride = gridDim.x * blockDim.x;
  int t = blockIdx.x * blockDim.x + threadIdx.x;
  for (int i = t; i < NN * NR; i += stride) g_S[i] = 0.f;
  for (int i = t; i < NN; i += stride) g_deg[i] = 0;
}

// w_e, S histogram, degree histogram (all layer-independent), fused.
__global__ void k_histwS(const float* __restrict__ etime, const int* __restrict__ eidx,
                         const int* __restrict__ etype, const float* __restrict__ plam,
                         const float* __restrict__ pbeta) {
  int e = blockIdx.x * blockDim.x + threadIdx.x;
  if (e >= NE) return;
  float w = plam[0] * expf(-pbeta[0] * fabsf(etime[e]));
  g_w[e] = w;
  int d = eidx[NE + e];
  int r = etype[e];
  atomicAdd(&g_S[d * NR + r], w);
  atomicAdd(&g_deg[d], 1);
}

// Exclusive scan of g_deg -> g_off, 2 levels. Chunk = 256.
__global__ void k_scanA() {
  __shared__ int s[256];
  int tid = threadIdx.x;
  int i = blockIdx.x * 256 + tid;
  int v = (i < NN) ? g_deg[i] : 0;
  s[tid] = v;
  __syncthreads();
  #pragma unroll
  for (int d = 1; d < 256; d <<= 1) {
    int t = (tid >= d) ? s[tid - d] : 0;
    __syncthreads();
    s[tid] += t;
    __syncthreads();
  }
  if (i < NN) g_off[i] = s[tid] - v;  // exclusive within chunk
  if (tid == 255) g_part[blockIdx.x] = s[255];
}

__global__ void k_scanB() {
  __shared__ int s[256];
  int tid = threadIdx.x;
  int v = (tid < NCHUNK) ? g_part[tid] : 0;
  s[tid] = v;
  __syncthreads();
  #pragma unroll
  for (int d = 1; d < 256; d <<= 1) {
    int t = (tid >= d) ? s[tid - d] : 0;
    __syncthreads();
    s[tid] += t;
    __syncthreads();
  }
  if (tid < NCHUNK) g_part[tid] = s[tid] - v;  // exclusive chunk bases
}

__global__ void k_scanC() {
  int i = blockIdx.x * 256 + threadIdx.x;
  if (i < NN) {
    int o = g_off[i] + g_part[i >> 8];
    g_off[i] = o;
    g_cur[i] = o;
  }
  if (i == 0) g_off[NN] = NE;
}

// Scatter edges into CSR order (by dst).
__global__ void k_fill(const int* __restrict__ eidx, const int* __restrict__ etype) {
  int e = blockIdx.x * blockDim.x + threadIdx.x;
  if (e >= NE) return;
  int d = eidx[NE + e];
  int pos = atomicAdd(&g_cur[d], 1);
  g_cmeta[pos] = eidx[e] | (etype[e] << 16);
  g_cw[pos] = g_w[e];
}

// ---------------------------------------------------------------------------
// FFMA GEMM helpers (unchanged; k_trans is at its FFMA roofline).
__device__ __forceinline__ void fillA(const float* __restrict__ A, int Kstride, int kofs,
                                      int row0, float* sA) {
  #pragma unroll 1
  for (int i = threadIdx.x; i < 1024; i += 256) {
    int r = i >> 4, c = i & 15;
    int row = row0 + r;
    float4 v = make_float4(0.f, 0.f, 0.f, 0.f);
    if (row < NN) v = *(const float4*)(A + (size_t)row * Kstride + kofs + c * 4);
    *(float4*)(sA + r * SA_STRIDE + c * 4) = v;
  }
}
__device__ __forceinline__ void fillW(const float* __restrict__ W, float* sW) {
  #pragma unroll 1
  for (int i = threadIdx.x; i < 1024; i += 256)
    ((float4*)sW)[i] = ((const float4*)W)[i];
}
__device__ __forceinline__ void mma64(const float* sA, const float* sW,
                                      float acc[4][4], int tx, int ty) {
  #pragma unroll 4
  for (int k = 0; k < 64; k += 4) {
    float4 a[4], w[4];
    #pragma unroll
    for (int i = 0; i < 4; i++)
      a[i] = *(const float4*)(sA + (ty * 4 + i) * SA_STRIDE + k);
    #pragma unroll
    for (int j = 0; j < 4; j++)
      w[j] = *(const float4*)(sW + (k + j) * 64 + tx * 4);
    #pragma unroll
    for (int i = 0; i < 4; i++) {
      acc[i][0] += a[i].x * w[0].x + a[i].y * w[1].x + a[i].z * w[2].x + a[i].w * w[3].x;
      acc[i][1] += a[i].x * w[0].y + a[i].y * w[1].y + a[i].z * w[2].y + a[i].w * w[3].y;
      acc[i][2] += a[i].x * w[0].z + a[i].y * w[1].z + a[i].z * w[2].z + a[i].w * w[3].z;
      acc[i][3] += a[i].x * w[0].w + a[i].y * w[1].w + a[i].z * w[2].w + a[i].w * w[3].w;
    }
  }
}

// emb0 = x @ field_W + field_b
__global__ void k_emb0(const float* __restrict__ x, const float* __restrict__ fW,
                       const float* __restrict__ fb) {
  __shared__ __align__(16) float sA[64 * SA_STRIDE];
  __shared__ __align__(16) float sW[64 * 64];
  __shared__ float sb[64];
  if (threadIdx.x < 64) sb[threadIdx.x] = fb[threadIdx.x];
  int tx = threadIdx.x & 15, ty = threadIdx.x >> 4;
  int row0 = blockIdx.x * 64;
  float acc[4][4] = {};
  #pragma unroll 1
  for (int k0 = 0; k0 < IND; k0 += 64) {
    __syncthreads();
    fillA(x, IND, k0, row0, sA);
    fillW(fW + (size_t)k0 * HD, sW);
    __syncthreads();
    mma64(sA, sW, acc, tx, ty);
  }
  #pragma unroll
  for (int i = 0; i < 4; i++) {
    int row = row0 + ty * 4 + i;
    if (row < NN) {
      float4 o = make_float4(acc[i][0] + sb[tx * 4 + 0], acc[i][1] + sb[tx * 4 + 1],
                             acc[i][2] + sb[tx * 4 + 2], acc[i][3] + sb[tx * 4 + 3]);
      *(float4*)(g_emb0 + (size_t)row * HD + tx * 4) = o;
    }
  }
}

// T[idx] = emb @ W_slice, one (row-tile, idx) GEMM per block. idx = blockIdx.y.
__global__ void k_trans(const float* __restrict__ relW, int layer) {
  __shared__ __align__(16) float sA[64 * SA_STRIDE];
  __shared__ __align__(16) float sW[64 * 64];
  const float* emb = (layer == 0) ? g_emb0 : g_emb1;
  int idx = blockIdx.y;
  int r = idx % 5, half = idx / 5;
  const float* W = relW + ((size_t)r * (2 * HD) + half * HD) * HD;
  int tx = threadIdx.x & 15, ty = threadIdx.x >> 4;
  int row0 = blockIdx.x * 64;
  fillA(emb, HD, 0, row0, sA);
  fillW(W, sW);
  __syncthreads();
  float acc[4][4] = {};
  mma64(sA, sW, acc, tx, ty);
  float* out = g_T + (size_t)idx * NN * HD;
  #pragma unroll
  for (int i = 0; i < 4; i++) {
    int row = row0 + ty * 4 + i;
    if (row < NN)
      *(float4*)(out + (size_t)row * HD + tx * 4) =
          make_float4(acc[i][0], acc[i][1], acc[i][2], acc[i][3]);
  }
}

// ---------------------------------------------------------------------------
// CSR edge pass fused with dst-term: one warp per node, no atomics.
// emb_out[n] = sum_{e in CSR[n]} w_e*TA[r_e][src_e] + sum_r S[n,r]*(TB_r[n]+b_r)
__global__ void __launch_bounds__(256) k_edge_csr(const float* __restrict__ relb, int layer) {
  int node = (blockIdx.x * 256 + threadIdx.x) >> 5;
  if (node >= NN) return;
  int lane = threadIdx.x & 31;
  int grp = lane >> 4, fl = lane & 15;

  int beg = __ldg(&g_off[node]);
  int end = __ldg(&g_off[node + 1]);

  float4 a = make_float4(0.f, 0.f, 0.f, 0.f);
  #pragma unroll 4
  for (int j = beg + grp; j < end; j += 2) {
    int m = __ldg(&g_cmeta[j]);
    float w = __ldg(&g_cw[j]);
    int src = m & 0xFFFF;
    int r = m >> 16;
    float4 v = __ldg((const float4*)(g_T + ((size_t)r * NN + src) * HD) + fl);
    a.x += w * v.x; a.y += w * v.y; a.z += w * v.z; a.w += w * v.w;
  }
  // reduce the two edge-groups
  a.x += __shfl_xor_sync(0xFFFFFFFF, a.x, 16);
  a.y += __shfl_xor_sync(0xFFFFFFFF, a.y, 16);
  a.z += __shfl_xor_sync(0xFFFFFFFF, a.z, 16);
  a.w += __shfl_xor_sync(0xFFFFFFFF, a.w, 16);

  if (grp == 0) {
    #pragma unroll
    for (int r = 0; r < NR; r++) {
      float s = __ldg(&g_S[node * NR + r]);
      float4 t4 = __ldg((const float4*)(g_T + ((size_t)(5 + r) * NN + node) * HD) + fl);
      float4 b4 = __ldg((const float4*)(relb + r * HD) + fl);
      a.x += s * (t4.x + b4.x);
      a.y += s * (t4.y + b4.y);
      a.z += s * (t4.z + b4.z);
      a.w += s * (t4.w + b4.w);
    }
    float* emb = (layer == 0) ? g_emb1 : g_emb2;
    *(float4*)(emb + (size_t)node * HD + fl * 4) = a;
  }
}

// out = sum_j leaky_relu(emb_j @ outW_j + outb_j), fused over j=0..2.
__global__ void k_out(const float* __restrict__ W0, const float* __restrict__ b0,
                      const float* __restrict__ W1, const float* __restrict__ b1,
                      const float* __restrict__ W2, const float* __restrict__ b2,
                      float* __restrict__ out) {
  __shared__ __align__(16) float sA[64 * SA_STRIDE];
  __shared__ __align__(16) float sW[64 * 64];
  __shared__ float sb[64];
  int tx = threadIdx.x & 15, ty = threadIdx.x >> 4;
  int row0 = blockIdx.x * 64;
  float o[4][4] = {};
  #pragma unroll 1
  for (int j = 0; j < 3; j++) {
    const float* emb = (j == 0) ? g_emb0 : (j == 1) ? g_emb1 : g_emb2;
    const float* W = (j == 0) ? W0 : (j == 1) ? W1 : W2;
    const float* b = (j == 0) ? b0 : (j == 1) ? b1 : b2;
    __syncthreads();
    if (threadIdx.x < 64) sb[threadIdx.x] = b[threadIdx.x];
    fillA(emb, HD, 0, row0, sA);
    fillW(W, sW);
    __syncthreads();
    float acc[4][4] = {};
    mma64(sA, sW, acc, tx, ty);
    #pragma unroll
    for (int i = 0; i < 4; i++)
      #pragma unroll
      for (int m = 0; m < 4; m++) {
        float z = acc[i][m] + sb[tx * 4 + m];
        o[i][m] += (z >= 0.f) ? z : NEG_SLOPE * z;
      }
  }
  #pragma unroll
  for (int i = 0; i < 4; i++) {
    int row = row0 + ty * 4 + i;
    if (row < NN)
      *(float4*)(out + (size_t)row * HD + tx * 4) =
          make_float4(o[i][0], o[i][1], o[i][2], o[i][3]);
  }
}

// ---------------------------------------------------------------------------
extern "C" void kernel_launch(void* const* d_in, const int* in_sizes, int n_in,
                              void* d_out, int out_size) {
  const float* x     = (const float*)d_in[0];
  const int*   eidx  = (const int*)d_in[1];
  const int*   etype = (const int*)d_in[2];
  const float* etime = (const float*)d_in[3];
  const float* fW    = (const float*)d_in[4];
  const float* fb    = (const float*)d_in[5];
  const float* rW1   = (const float*)d_in[6];
  const float* rb1   = (const float*)d_in[7];
  const float* rW2   = (const float*)d_in[8];
  const float* rb2   = (const float*)d_in[9];
  const float* oW0   = (const float*)d_in[10];
  const float* ob0   = (const float*)d_in[11];
  const float* oW1   = (const float*)d_in[12];
  const float* ob1   = (const float*)d_in[13];
  const float* oW2   = (const float*)d_in[14];
  const float* ob2   = (const float*)d_in[15];
  const float* lam   = (const float*)d_in[16];
  const float* beta  = (const float*)d_in[17];
  float* out = (float*)d_out;

  const int GB = (NN + 63) / 64;  // 782 row tiles
  dim3 gt(GB, 10);
  const int EB = (NE + 255) / 256;        // 6250
  const int WB = (NN * 32 + 255) / 256;   // 6250 (one warp per node)

  // CSR build (layer-independent)
  k_zero<<<1024, 256>>>();
  k_histwS<<<EB, 256>>>(etime, eidx, etype, lam, beta);
  k_scanA<<<NCHUNK, 256>>>();
  k_scanB<<<1, 256>>>();
  k_scanC<<<NCHUNK, 256>>>();
  k_fill<<<EB, 256>>>(eidx, etype);

  k_emb0<<<GB, 256>>>(x, fW, fb);

  // layer 1
  k_trans<<<gt, 256>>>(rW1, 0);
  k_edge_csr<<<WB, 256>>>(rb1, 0);

  // layer 2
  k_trans<<<gt, 256>>>(rW2, 1);
  k_edge_csr<<<WB, 256>>>(rb2, 1);

  k_out<<<GB, 256>>>(oW0, ob0, oW1, ob1, oW2, ob2, out);
}

// round 8
// speedup vs baseline: 1.9992x; 1.1268x over previous
#include <cuda_runtime.h>
#include <cstdint>

#define NN 50000
#define NE 1600000
#define IND 128
#define HD 64
#define NR 5
#define SA_STRIDE 68
#define NEG_SLOPE 0.01f
#define NCHUNK 196   // ceil(50000/256)

// ---- scratch (device globals; no allocation allowed) ----
__device__ float g_w[NE];
__device__ float g_S[NN * NR];
__device__ int   g_deg[NN];
__device__ int   g_off[NN + 1];
__device__ int   g_part[256];
__device__ int   g_cur[NN];
__device__ int   g_cmeta[NE];     // src | (r<<16)
__device__ float g_cw[NE];
__device__ float g_emb0[NN * HD];
__device__ float g_emb1[NN * HD];
__device__ float g_emb2[NN * HD];
__device__ float g_T[(size_t)10 * NN * HD];  // TA_r at idx r (0..4), TB_r at idx 5+r

// ---------------------------------------------------------------------------
__global__ void k_zero() {
  int stride = gridDim.x * blockDim.x;
  int t = blockIdx.x * blockDim.x + threadIdx.x;
  for (int i = t; i < NN * NR; i += stride) g_S[i] = 0.f;
  for (int i = t; i < NN; i += stride) g_deg[i] = 0;
}

__global__ void k_histwS(const float* __restrict__ etime, const int* __restrict__ eidx,
                         const int* __restrict__ etype, const float* __restrict__ plam,
                         const float* __restrict__ pbeta) {
  int e = blockIdx.x * blockDim.x + threadIdx.x;
  if (e >= NE) return;
  float w = plam[0] * expf(-pbeta[0] * fabsf(etime[e]));
  g_w[e] = w;
  int d = eidx[NE + e];
  int r = etype[e];
  atomicAdd(&g_S[d * NR + r], w);
  atomicAdd(&g_deg[d], 1);
}

__global__ void k_scanA() {
  __shared__ int s[256];
  int tid = threadIdx.x;
  int i = blockIdx.x * 256 + tid;
  int v = (i < NN) ? g_deg[i] : 0;
  s[tid] = v;
  __syncthreads();
  #pragma unroll
  for (int d = 1; d < 256; d <<= 1) {
    int t = (tid >= d) ? s[tid - d] : 0;
    __syncthreads();
    s[tid] += t;
    __syncthreads();
  }
  if (i < NN) g_off[i] = s[tid] - v;
  if (tid == 255) g_part[blockIdx.x] = s[255];
}

__global__ void k_scanB() {
  __shared__ int s[256];
  int tid = threadIdx.x;
  int v = (tid < NCHUNK) ? g_part[tid] : 0;
  s[tid] = v;
  __syncthreads();
  #pragma unroll
  for (int d = 1; d < 256; d <<= 1) {
    int t = (tid >= d) ? s[tid - d] : 0;
    __syncthreads();
    s[tid] += t;
    __syncthreads();
  }
  if (tid < NCHUNK) g_part[tid] = s[tid] - v;
}

__global__ void k_scanC() {
  int i = blockIdx.x * 256 + threadIdx.x;
  if (i < NN) {
    int o = g_off[i] + g_part[i >> 8];
    g_off[i] = o;
    g_cur[i] = o;
  }
  if (i == 0) g_off[NN] = NE;
}

__global__ void k_fill(const int* __restrict__ eidx, const int* __restrict__ etype) {
  int e = blockIdx.x * blockDim.x + threadIdx.x;
  if (e >= NE) return;
  int d = eidx[NE + e];
  int pos = atomicAdd(&g_cur[d], 1);
  g_cmeta[pos] = eidx[e] | (etype[e] << 16);
  g_cw[pos] = g_w[e];
}

// ---------------------------------------------------------------------------
// tf32 helpers (validated in R3: rel_err 9.9e-7)
__device__ __forceinline__ uint32_t f2tf(float f) {
  uint32_t r;
  asm("cvt.rna.tf32.f32 %0, %1;" : "=r"(r) : "f"(f));
  return r;
}
__device__ __forceinline__ void split_tf(float f, uint32_t& hi, uint32_t& lo) {
  hi = f2tf(f);
  lo = f2tf(f - __uint_as_float(hi));
}
__device__ __forceinline__ void mma_tf32(float c[4], uint32_t a0, uint32_t a1,
                                         uint32_t a2, uint32_t a3,
                                         uint32_t b0, uint32_t b1) {
  asm volatile(
      "mma.sync.aligned.m16n8k8.row.col.f32.tf32.tf32.f32 "
      "{%0,%1,%2,%3}, {%4,%5,%6,%7}, {%8,%9}, {%0,%1,%2,%3};"
      : "+f"(c[0]), "+f"(c[1]), "+f"(c[2]), "+f"(c[3])
      : "r"(a0), "r"(a1), "r"(a2), "r"(a3), "r"(b0), "r"(b1));
}

// k_trans: T[idx] = emb @ W_slice, 3xTF32 tensor cores.
// Block: 256 threads (8 warps), 128 rows x 64 cols, one idx per block.
// smem: raw A tile (fp32, padded) + B fragments pre-split in fragment order.
#define TRANS_SMEM (128 * SA_STRIDE * 4 + 8 * 8 * 32 * 16)  // 34816 + 32768 = 67584
__global__ void __launch_bounds__(256) k_trans_mma(const float* __restrict__ relW, int layer) {
  extern __shared__ __align__(16) float smem[];
  float* sA = smem;                                   // [128][SA_STRIDE]
  uint4* sBf = (uint4*)(smem + 128 * SA_STRIDE);      // [ks][nc][lane] -> (b0h,b1h,b0l,b1l)

  const float* emb = (layer == 0) ? g_emb0 : g_emb1;
  int idx = blockIdx.y;
  int rr = idx % 5, half = idx / 5;
  const float* W = relW + ((size_t)rr * (2 * HD) + half * HD) * HD;

  int tid = threadIdx.x;
  int lane = tid & 31, warp = tid >> 5;
  int g = lane >> 2, tg = lane & 3;
  int row0 = blockIdx.x * 128;

  // Fill A tile: 128 rows x 64 cols, coalesced float4, zero-pad OOB rows.
  #pragma unroll 1
  for (int i = tid; i < 128 * 16; i += 256) {
    int r = i >> 4, c = i & 15;
    float4 v = make_float4(0.f, 0.f, 0.f, 0.f);
    if (row0 + r < NN) v = *(const float4*)(emb + (size_t)(row0 + r) * HD + c * 4);
    *(float4*)(sA + r * SA_STRIDE + c * 4) = v;
  }

  // Fill B fragments: pre-split tf32 hi/lo, arranged so inner loop does 1 LDS.128.
  #pragma unroll 1
  for (int s = tid; s < 8 * 8 * 32; s += 256) {
    int ks = s >> 8;
    int nc = (s >> 5) & 7;
    int ln = s & 31;
    int lg = ln >> 2, ltg = ln & 3;
    int k1 = ks * 8 + ltg, k2 = k1 + 4;
    int n = nc * 8 + lg;
    uint32_t h1, l1, h2, l2;
    split_tf(__ldg(&W[k1 * HD + n]), h1, l1);
    split_tf(__ldg(&W[k2 * HD + n]), h2, l2);
    sBf[s] = make_uint4(h1, h2, l1, l2);
  }
  __syncthreads();

  int wrow = warp * 16;
  float acc[8][4] = {};
  #pragma unroll 1
  for (int ks = 0; ks < 8; ks++) {
    int kb = ks * 8;
    float af0 = sA[(wrow + g) * SA_STRIDE + kb + tg];
    float af1 = sA[(wrow + g + 8) * SA_STRIDE + kb + tg];
    float af2 = sA[(wrow + g) * SA_STRIDE + kb + tg + 4];
    float af3 = sA[(wrow + g + 8) * SA_STRIDE + kb + tg + 4];
    uint32_t ah0, al0, ah1, al1, ah2, al2, ah3, al3;
    split_tf(af0, ah0, al0);
    split_tf(af1, ah1, al1);
    split_tf(af2, ah2, al2);
    split_tf(af3, ah3, al3);
    const uint4* bp = sBf + ks * 8 * 32 + lane;
    #pragma unroll
    for (int nc = 0; nc < 8; nc++) {
      uint4 b = bp[nc * 32];
      mma_tf32(acc[nc], ah0, ah1, ah2, ah3, b.x, b.y);  // hi*hi
      mma_tf32(acc[nc], ah0, ah1, ah2, ah3, b.z, b.w);  // hi*lo
      mma_tf32(acc[nc], al0, al1, al2, al3, b.x, b.y);  // lo*hi
    }
  }

  // Writeback (same mapping as validated R3 kernel).
  float* out = g_T + (size_t)idx * NN * HD;
  int ra = row0 + wrow + g;
  int rb = ra + 8;
  #pragma unroll
  for (int nc = 0; nc < 8; nc++) {
    int col = nc * 8 + 2 * tg;
    if (ra < NN)
      *(float2*)(out + (size_t)ra * HD + col) = make_float2(acc[nc][0], acc[nc][1]);
    if (rb < NN)
      *(float2*)(out + (size_t)rb * HD + col) = make_float2(acc[nc][2], acc[nc][3]);
  }
}

// ---------------------------------------------------------------------------
// FFMA GEMM helpers (emb0 / out remain FFMA).
__device__ __forceinline__ void fillA(const float* __restrict__ A, int Kstride, int kofs,
                                      int row0, float* sA) {
  #pragma unroll 1
  for (int i = threadIdx.x; i < 1024; i += 256) {
    int r = i >> 4, c = i & 15;
    int row = row0 + r;
    float4 v = make_float4(0.f, 0.f, 0.f, 0.f);
    if (row < NN) v = *(const float4*)(A + (size_t)row * Kstride + kofs + c * 4);
    *(float4*)(sA + r * SA_STRIDE + c * 4) = v;
  }
}
__device__ __forceinline__ void fillW(const float* __restrict__ W, float* sW) {
  #pragma unroll 1
  for (int i = threadIdx.x; i < 1024; i += 256)
    ((float4*)sW)[i] = ((const float4*)W)[i];
}
__device__ __forceinline__ void mma64(const float* sA, const float* sW,
                                      float acc[4][4], int tx, int ty) {
  #pragma unroll 4
  for (int k = 0; k < 64; k += 4) {
    float4 a[4], w[4];
    #pragma unroll
    for (int i = 0; i < 4; i++)
      a[i] = *(const float4*)(sA + (ty * 4 + i) * SA_STRIDE + k);
    #pragma unroll
    for (int j = 0; j < 4; j++)
      w[j] = *(const float4*)(sW + (k + j) * 64 + tx * 4);
    #pragma unroll
    for (int i = 0; i < 4; i++) {
      acc[i][0] += a[i].x * w[0].x + a[i].y * w[1].x + a[i].z * w[2].x + a[i].w * w[3].x;
      acc[i][1] += a[i].x * w[0].y + a[i].y * w[1].y + a[i].z * w[2].y + a[i].w * w[3].y;
      acc[i][2] += a[i].x * w[0].z + a[i].y * w[1].z + a[i].z * w[2].z + a[i].w * w[3].z;
      acc[i][3] += a[i].x * w[0].w + a[i].y * w[1].w + a[i].z * w[2].w + a[i].w * w[3].w;
    }
  }
}

// emb0 = x @ field_W + field_b
__global__ void k_emb0(const float* __restrict__ x, const float* __restrict__ fW,
                       const float* __restrict__ fb) {
  __shared__ __align__(16) float sA[64 * SA_STRIDE];
  __shared__ __align__(16) float sW[64 * 64];
  __shared__ float sb[64];
  if (threadIdx.x < 64) sb[threadIdx.x] = fb[threadIdx.x];
  int tx = threadIdx.x & 15, ty = threadIdx.x >> 4;
  int row0 = blockIdx.x * 64;
  float acc[4][4] = {};
  #pragma unroll 1
  for (int k0 = 0; k0 < IND; k0 += 64) {
    __syncthreads();
    fillA(x, IND, k0, row0, sA);
    fillW(fW + (size_t)k0 * HD, sW);
    __syncthreads();
    mma64(sA, sW, acc, tx, ty);
  }
  #pragma unroll
  for (int i = 0; i < 4; i++) {
    int row = row0 + ty * 4 + i;
    if (row < NN) {
      float4 o = make_float4(acc[i][0] + sb[tx * 4 + 0], acc[i][1] + sb[tx * 4 + 1],
                             acc[i][2] + sb[tx * 4 + 2], acc[i][3] + sb[tx * 4 + 3]);
      *(float4*)(g_emb0 + (size_t)row * HD + tx * 4) = o;
    }
  }
}

// ---------------------------------------------------------------------------
// CSR edge pass fused with dst-term (one warp per node, no atomics).
__global__ void __launch_bounds__(256) k_edge_csr(const float* __restrict__ relb, int layer) {
  int node = (blockIdx.x * 256 + threadIdx.x) >> 5;
  if (node >= NN) return;
  int lane = threadIdx.x & 31;
  int grp = lane >> 4, fl = lane & 15;

  int beg = __ldg(&g_off[node]);
  int end = __ldg(&g_off[node + 1]);

  float4 a = make_float4(0.f, 0.f, 0.f, 0.f);
  #pragma unroll 4
  for (int j = beg + grp; j < end; j += 2) {
    int m = __ldg(&g_cmeta[j]);
    float w = __ldg(&g_cw[j]);
    int src = m & 0xFFFF;
    int r = m >> 16;
    float4 v = __ldg((const float4*)(g_T + ((size_t)r * NN + src) * HD) + fl);
    a.x += w * v.x; a.y += w * v.y; a.z += w * v.z; a.w += w * v.w;
  }
  a.x += __shfl_xor_sync(0xFFFFFFFF, a.x, 16);
  a.y += __shfl_xor_sync(0xFFFFFFFF, a.y, 16);
  a.z += __shfl_xor_sync(0xFFFFFFFF, a.z, 16);
  a.w += __shfl_xor_sync(0xFFFFFFFF, a.w, 16);

  if (grp == 0) {
    #pragma unroll
    for (int r = 0; r < NR; r++) {
      float s = __ldg(&g_S[node * NR + r]);
      float4 t4 = __ldg((const float4*)(g_T + ((size_t)(5 + r) * NN + node) * HD) + fl);
      float4 b4 = __ldg((const float4*)(relb + r * HD) + fl);
      a.x += s * (t4.x + b4.x);
      a.y += s * (t4.y + b4.y);
      a.z += s * (t4.z + b4.z);
      a.w += s * (t4.w + b4.w);
    }
    float* emb = (layer == 0) ? g_emb1 : g_emb2;
    *(float4*)(emb + (size_t)node * HD + fl * 4) = a;
  }
}

// out = sum_j leaky_relu(emb_j @ outW_j + outb_j), fused over j=0..2.
__global__ void k_out(const float* __restrict__ W0, const float* __restrict__ b0,
                      const float* __restrict__ W1, const float* __restrict__ b1,
                      const float* __restrict__ W2, const float* __restrict__ b2,
                      float* __restrict__ out) {
  __shared__ __align__(16) float sA[64 * SA_STRIDE];
  __shared__ __align__(16) float sW[64 * 64];
  __shared__ float sb[64];
  int tx = threadIdx.x & 15, ty = threadIdx.x >> 4;
  int row0 = blockIdx.x * 64;
  float o[4][4] = {};
  #pragma unroll 1
  for (int j = 0; j < 3; j++) {
    const float* emb = (j == 0) ? g_emb0 : (j == 1) ? g_emb1 : g_emb2;
    const float* W = (j == 0) ? W0 : (j == 1) ? W1 : W2;
    const float* b = (j == 0) ? b0 : (j == 1) ? b1 : b2;
    __syncthreads();
    if (threadIdx.x < 64) sb[threadIdx.x] = b[threadIdx.x];
    fillA(emb, HD, 0, row0, sA);
    fillW(W, sW);
    __syncthreads();
    float acc[4][4] = {};
    mma64(sA, sW, acc, tx, ty);
    #pragma unroll
    for (int i = 0; i < 4; i++)
      #pragma unroll
      for (int m = 0; m < 4; m++) {
        float z = acc[i][m] + sb[tx * 4 + m];
        o[i][m] += (z >= 0.f) ? z : NEG_SLOPE * z;
      }
  }
  #pragma unroll
  for (int i = 0; i < 4; i++) {
    int row = row0 + ty * 4 + i;
    if (row < NN)
      *(float4*)(out + (size_t)row * HD + tx * 4) =
          make_float4(o[i][0], o[i][1], o[i][2], o[i][3]);
  }
}

// ---------------------------------------------------------------------------
extern "C" void kernel_launch(void* const* d_in, const int* in_sizes, int n_in,
                              void* d_out, int out_size) {
  const float* x     = (const float*)d_in[0];
  const int*   eidx  = (const int*)d_in[1];
  const int*   etype = (const int*)d_in[2];
  const float* etime = (const float*)d_in[3];
  const float* fW    = (const float*)d_in[4];
  const float* fb    = (const float*)d_in[5];
  const float* rW1   = (const float*)d_in[6];
  const float* rb1   = (const float*)d_in[7];
  const float* rW2   = (const float*)d_in[8];
  const float* rb2   = (const float*)d_in[9];
  const float* oW0   = (const float*)d_in[10];
  const float* ob0   = (const float*)d_in[11];
  const float* oW1   = (const float*)d_in[12];
  const float* ob1   = (const float*)d_in[13];
  const float* oW2   = (const float*)d_in[14];
  const float* ob2   = (const float*)d_in[15];
  const float* lam   = (const float*)d_in[16];
  const float* beta  = (const float*)d_in[17];
  float* out = (float*)d_out;

  const int GB = (NN + 63) / 64;          // 782 (FFMA kernels)
  const int TB = (NN + 127) / 128;        // 391 (tensor k_trans)
  dim3 gt(TB, 10);
  const int EB = (NE + 255) / 256;        // 6250
  const int WB = (NN * 32 + 255) / 256;   // one warp per node

  cudaFuncSetAttribute(k_trans_mma, cudaFuncAttributeMaxDynamicSharedMemorySize, TRANS_SMEM);

  // CSR build (layer-independent)
  k_zero<<<1024, 256>>>();
  k_histwS<<<EB, 256>>>(etime, eidx, etype, lam, beta);
  k_scanA<<<NCHUNK, 256>>>();
  k_scanB<<<1, 256>>>();
  k_scanC<<<NCHUNK, 256>>>();
  k_fill<<<EB, 256>>>(eidx, etype);

  k_emb0<<<GB, 256>>>(x, fW, fb);

  // layer 1
  k_trans_mma<<<gt, 256, TRANS_SMEM>>>(rW1, 0);
  k_edge_csr<<<WB, 256>>>(rb1, 0);

  // layer 2
  k_trans_mma<<<gt, 256, TRANS_SMEM>>>(rW2, 1);
  k_edge_csr<<<WB, 256>>>(rb2, 1);

  k_out<<<GB, 256>>>(oW0, ob0, oW1, ob1, oW2, ob2, out);
}